// round 3
// baseline (speedup 1.0000x reference)
#include <cuda_runtime.h>
#include <math.h>
#include <stdint.h>

// Problem constants
#define BBATCH 8
#define SQLEN  256
#define SKVLEN 1024
#define DMODEL 1024
#define NHEADS 16
#define DHEAD  64
#define DFFN   4096

#define QROWS  (BBATCH*SQLEN)    // 2048
#define KVROWS (BBATCH*SKVLEN)   // 8192
#define OUT_ELEMS  ((size_t)QROWS*DMODEL)
#define ATTN_ELEMS ((size_t)BBATCH*NHEADS*SQLEN*SKVLEN)

// ----------------------------- scratch ---------------------------------
__device__ float g_qln [QROWS*DMODEL];
__device__ float g_kvln[KVROWS*DMODEL];
__device__ float g_Qh  [QROWS*DMODEL];     // [b][h][sq][dk]
__device__ float g_Kh  [KVROWS*DMODEL];    // [b][h][skv][dk]
__device__ float g_Vt  [KVROWS*DMODEL];    // [b][h][dk][skv]
__device__ float g_ctx [QROWS*DMODEL];
__device__ float g_x   [QROWS*DMODEL];
__device__ float g_y   [QROWS*DMODEL];
__device__ float g_h   [QROWS*DFFN];
__device__ float g_Wqt[DMODEL*DMODEL];
__device__ float g_Wkt[DMODEL*DMODEL];
__device__ float g_Wvt[DMODEL*DMODEL];
__device__ float g_Wot[DMODEL*DMODEL];
__device__ float g_W1t[DFFN*DMODEL];
__device__ float g_W2t[DMODEL*DFFN];
__device__ float g_attn_fb[BBATCH*NHEADS*SQLEN*SKVLEN];

// ----------------------------- transpose: Wt[n][k] = W[k][n] ------------
__global__ void __launch_bounds__(256) transpose_kernel(const float* __restrict__ W,
                                                        float* __restrict__ Wt,
                                                        int K, int N) {
    __shared__ float t[32][33];
    const int n0 = blockIdx.x * 32, k0 = blockIdx.y * 32;
    const int x = threadIdx.x & 31, y = threadIdx.x >> 5;
    #pragma unroll
    for (int i = 0; i < 32; i += 8)
        t[y + i][x] = W[(size_t)(k0 + y + i) * N + n0 + x];
    __syncthreads();
    #pragma unroll
    for (int i = 0; i < 32; i += 8)
        Wt[(size_t)(n0 + y + i) * K + k0 + x] = t[x][y + i];
}

// ----------------------------- LayerNorm --------------------------------
__global__ void __launch_bounds__(256) ln_kernel(const float* __restrict__ x,
                                                 const float* __restrict__ g,
                                                 const float* __restrict__ b,
                                                 float* __restrict__ y) {
    __shared__ float ssum[256];
    __shared__ float ssq [256];
    const int row = blockIdx.x;
    const int tid = threadIdx.x;
    const float4 xv = ((const float4*)(x + (size_t)row*DMODEL))[tid];
    ssum[tid] = xv.x + xv.y + xv.z + xv.w;
    ssq [tid] = xv.x*xv.x + xv.y*xv.y + xv.z*xv.z + xv.w*xv.w;
    __syncthreads();
    for (int st = 128; st > 0; st >>= 1) {
        if (tid < st) { ssum[tid] += ssum[tid+st]; ssq[tid] += ssq[tid+st]; }
        __syncthreads();
    }
    const float mu  = ssum[0] * (1.0f/DMODEL);
    const float var = ssq[0]  * (1.0f/DMODEL) - mu*mu;
    const float inv = rsqrtf(var + 1e-5f);
    const float4 gv = ((const float4*)g)[tid];
    const float4 bv = ((const float4*)b)[tid];
    float4 o;
    o.x = (xv.x - mu)*inv*gv.x + bv.x;
    o.y = (xv.y - mu)*inv*gv.y + bv.y;
    o.z = (xv.z - mu)*inv*gv.z + bv.z;
    o.w = (xv.w - mu)*inv*gv.w + bv.w;
    ((float4*)(y + (size_t)row*DMODEL))[tid] = o;
}

// ----------------------------- softmax (rows of 1024, in place) ---------
__global__ void __launch_bounds__(256) softmax_kernel(float* __restrict__ attn) {
    __shared__ float red[256];
    const size_t row = blockIdx.x;
    float4* p = (float4*)(attn + row*(size_t)SKVLEN);
    const int tid = threadIdx.x;
    float4 v = p[tid];
    float m = fmaxf(fmaxf(v.x, v.y), fmaxf(v.z, v.w));
    red[tid] = m; __syncthreads();
    for (int st = 128; st > 0; st >>= 1) {
        if (tid < st) red[tid] = fmaxf(red[tid], red[tid+st]);
        __syncthreads();
    }
    m = red[0];
    __syncthreads();
    v.x = __expf(v.x - m); v.y = __expf(v.y - m);
    v.z = __expf(v.z - m); v.w = __expf(v.w - m);
    red[tid] = v.x + v.y + v.z + v.w; __syncthreads();
    for (int st = 128; st > 0; st >>= 1) {
        if (tid < st) red[tid] += red[tid+st];
        __syncthreads();
    }
    const float inv = 1.0f / red[0];
    v.x *= inv; v.y *= inv; v.z *= inv; v.w *= inv;
    p[tid] = v;
}

// ----------------------------- tf32 MMA helpers --------------------------
__device__ __forceinline__ uint32_t f2tf32(uint32_t bits) {
    uint32_t r;
    asm("cvt.rna.tf32.f32 %0, %1;" : "=r"(r) : "f"(__uint_as_float(bits)));
    return r;
}

__device__ __forceinline__ void ldsm4(uint32_t (&d)[4], uint32_t addr) {
    asm volatile("ldmatrix.sync.aligned.m8n8.x4.shared.b16 {%0,%1,%2,%3}, [%4];"
        : "=r"(d[0]), "=r"(d[1]), "=r"(d[2]), "=r"(d[3]) : "r"(addr));
}

__device__ __forceinline__ void mma_tf32(float (&c)[4], const uint32_t (&a)[4],
                                         const uint32_t* b) {
    asm volatile("mma.sync.aligned.m16n8k8.row.col.f32.tf32.tf32.f32 "
        "{%0,%1,%2,%3},{%4,%5,%6,%7},{%8,%9},{%0,%1,%2,%3};"
        : "+f"(c[0]), "+f"(c[1]), "+f"(c[2]), "+f"(c[3])
        : "r"(a[0]), "r"(a[1]), "r"(a[2]), "r"(a[3]), "r"(b[0]), "r"(b[1]));
}

// Epilogue modes:
// 0: C[row*N+col] = v + bias[col]
// 1: gelu(v + bias[col])
// 2: v + bias[col] + res[row*N+col]
// 3: Q head split (seq 256):  Qh[b][h][sq][dk]
// 4: K head split (seq 1024): Kh[b][h][skv][dk]
// 5: V head split, transposed: Vt[b][h][dk][skv]
// 6: scores: attn[bz][row][col] = v * 0.125
// 7: ctx: row-major [b*SQ+row][h*64+col]
template<int MODE>
__device__ __forceinline__ void store_elem(float* __restrict__ C,
                                           const float* __restrict__ bias,
                                           const float* __restrict__ res,
                                           int N, int bz, int row, int col, float v) {
    if (MODE == 0) {
        C[(size_t)row*N + col] = v + bias[col];
    } else if (MODE == 1) {
        float x = v + bias[col];
        C[(size_t)row*N + col] = 0.5f * x * (1.0f + erff(x * 0.70710678118654752f));
    } else if (MODE == 2) {
        C[(size_t)row*N + col] = v + bias[col] + res[(size_t)row*N + col];
    } else if (MODE == 3) {
        size_t idx = (size_t)(row >> 8)*(NHEADS*SQLEN*DHEAD) + (size_t)(col >> 6)*(SQLEN*DHEAD)
                   + (size_t)(row & 255)*DHEAD + (col & 63);
        C[idx] = v + bias[col];
    } else if (MODE == 4) {
        size_t idx = (size_t)(row >> 10)*(NHEADS*SKVLEN*DHEAD) + (size_t)(col >> 6)*(SKVLEN*DHEAD)
                   + (size_t)(row & 1023)*DHEAD + (col & 63);
        C[idx] = v + bias[col];
    } else if (MODE == 5) {
        size_t idx = (size_t)(row >> 10)*(NHEADS*DHEAD*SKVLEN) + (size_t)(col >> 6)*(DHEAD*SKVLEN)
                   + (size_t)(col & 63)*SKVLEN + (row & 1023);
        C[idx] = v + bias[col];
    } else if (MODE == 6) {
        C[(size_t)bz*(SQLEN*SKVLEN) + (size_t)row*SKVLEN + col] = v * 0.125f;
    } else if (MODE == 7) {
        size_t r = (size_t)(bz >> 4)*SQLEN + row;
        size_t c = (size_t)(bz & 15)*DHEAD + col;
        C[r*DMODEL + c] = v;
    }
}

// ---------------- tf32 NT GEMM: C = A[M,K] * B[N,K]^T (+epilogue) -------
// BK=16, 2-stage cp.async pipeline, 256 threads (8 warps).
template<int BM, int BN, int WM, int WN, int MODE>
__global__ void __launch_bounds__(256, 2) mma_nt_kernel(
    const float* __restrict__ Ag, const float* __restrict__ Bg,
    const float* __restrict__ bias, const float* __restrict__ res,
    float* __restrict__ Cg, int M, int N, int K,
    long sA, long sB)
{
    constexpr int AST = 20;                 // 16 + 4 pad floats
    constexpr int MT = BM / (WM * 16);
    constexpr int NT = BN / (WN * 8);
    __shared__ __align__(16) float As[2][BM][AST];
    __shared__ __align__(16) float Bs[2][BN][AST];

    const int tid  = threadIdx.x;
    const int warp = tid >> 5, lane = tid & 31;
    const int wm0 = (warp % WM) * (BM / WM);
    const int wn0 = (warp / WM) * (BN / WN);
    const int bm0 = blockIdx.y * BM;
    const int bn0 = blockIdx.x * BN;
    const int bz  = blockIdx.z;
    const float* A = Ag + (size_t)bz * sA;
    const float* B = Bg + (size_t)bz * sB;

    const uint32_t sA32 = (uint32_t)__cvta_generic_to_shared(&As[0][0][0]);
    const uint32_t sB32 = (uint32_t)__cvta_generic_to_shared(&Bs[0][0][0]);

    float acc[MT][NT][4];
    #pragma unroll
    for (int i = 0; i < MT; ++i)
        #pragma unroll
        for (int j = 0; j < NT; ++j)
            { acc[i][j][0]=0.f; acc[i][j][1]=0.f; acc[i][j][2]=0.f; acc[i][j][3]=0.f; }

    const int KT = K >> 4;

    auto prefetch = [&](int buf, int kt) {
        const float* Ak = A + (kt << 4);
        for (int i = tid; i < BM*4; i += 256) {
            int r = i >> 2, c = i & 3;
            uint32_t dst = sA32 + (uint32_t)(((buf*BM + r)*AST + c*4) * 4);
            const float* src = Ak + (size_t)(bm0 + r)*K + c*4;
            asm volatile("cp.async.cg.shared.global [%0], [%1], 16;" :: "r"(dst), "l"(src));
        }
        const float* Bk = B + (kt << 4);
        for (int i = tid; i < BN*4; i += 256) {
            int r = i >> 2, c = i & 3;
            uint32_t dst = sB32 + (uint32_t)(((buf*BN + r)*AST + c*4) * 4);
            const float* src = Bk + (size_t)(bn0 + r)*K + c*4;
            asm volatile("cp.async.cg.shared.global [%0], [%1], 16;" :: "r"(dst), "l"(src));
        }
        asm volatile("cp.async.commit_group;");
    };

    prefetch(0, 0);

    for (int kt = 0; kt < KT; ++kt) {
        const int buf = kt & 1;
        if (kt + 1 < KT) {
            prefetch(buf ^ 1, kt + 1);
            asm volatile("cp.async.wait_group 1;");
        } else {
            asm volatile("cp.async.wait_group 0;");
        }
        __syncthreads();

        #pragma unroll
        for (int ks = 0; ks < 2; ++ks) {
            uint32_t af[MT][4];
            uint32_t bf[NT][2];
            const int lr = lane & 15;
            const int lc = (lane >> 4) * 4;
            #pragma unroll
            for (int mt = 0; mt < MT; ++mt) {
                uint32_t addr = sA32 + (uint32_t)((((buf*BM) + wm0 + mt*16 + lr)*AST + ks*8 + lc) * 4);
                ldsm4(af[mt], addr);
                af[mt][0] = f2tf32(af[mt][0]); af[mt][1] = f2tf32(af[mt][1]);
                af[mt][2] = f2tf32(af[mt][2]); af[mt][3] = f2tf32(af[mt][3]);
            }
            const int br = (lane & 7) + ((lane & 16) ? 8 : 0);
            const int bc = (lane & 8) ? 4 : 0;
            #pragma unroll
            for (int nt2 = 0; nt2 < NT/2; ++nt2) {
                uint32_t d[4];
                uint32_t addr = sB32 + (uint32_t)((((buf*BN) + wn0 + nt2*16 + br)*AST + ks*8 + bc) * 4);
                ldsm4(d, addr);
                bf[nt2*2  ][0] = f2tf32(d[0]); bf[nt2*2  ][1] = f2tf32(d[1]);
                bf[nt2*2+1][0] = f2tf32(d[2]); bf[nt2*2+1][1] = f2tf32(d[3]);
            }
            #pragma unroll
            for (int mt = 0; mt < MT; ++mt)
                #pragma unroll
                for (int nt = 0; nt < NT; ++nt)
                    mma_tf32(acc[mt][nt], af[mt], bf[nt]);
        }
        __syncthreads();
    }

    // epilogue
    const int g = lane >> 2, t = lane & 3;
    #pragma unroll
    for (int mt = 0; mt < MT; ++mt) {
        #pragma unroll
        for (int nt = 0; nt < NT; ++nt) {
            const int r0 = bm0 + wm0 + mt*16 + g;
            const int c0 = bn0 + wn0 + nt*8 + t*2;
            store_elem<MODE>(Cg, bias, res, N, bz, r0,     c0,     acc[mt][nt][0]);
            store_elem<MODE>(Cg, bias, res, N, bz, r0,     c0 + 1, acc[mt][nt][1]);
            store_elem<MODE>(Cg, bias, res, N, bz, r0 + 8, c0,     acc[mt][nt][2]);
            store_elem<MODE>(Cg, bias, res, N, bz, r0 + 8, c0 + 1, acc[mt][nt][3]);
        }
    }
}

// ----------------------------- launch ------------------------------------
extern "C" void kernel_launch(void* const* d_in, const int* in_sizes, int n_in,
                              void* d_out, int out_size) {
    const float* memory = (const float*)d_in[0];
    const float* q      = (const float*)d_in[1];
    const float* Wq = (const float*)d_in[2];  const float* bq = (const float*)d_in[3];
    const float* Wk = (const float*)d_in[4];  const float* bk = (const float*)d_in[5];
    const float* Wv = (const float*)d_in[6];  const float* bv = (const float*)d_in[7];
    const float* Wo = (const float*)d_in[8];  const float* bo = (const float*)d_in[9];
    const float* g_kv = (const float*)d_in[10]; const float* b_kv = (const float*)d_in[11];
    const float* g_q  = (const float*)d_in[12]; const float* b_q  = (const float*)d_in[13];
    const float* g_ff = (const float*)d_in[14]; const float* b_ff = (const float*)d_in[15];
    const float* W1 = (const float*)d_in[16]; const float* b1 = (const float*)d_in[17];
    const float* W2 = (const float*)d_in[18]; const float* b2 = (const float*)d_in[19];

    float *p_qln, *p_kvln, *p_Qh, *p_Kh, *p_Vt, *p_ctx, *p_x, *p_y, *p_h;
    float *p_Wqt, *p_Wkt, *p_Wvt, *p_Wot, *p_W1t, *p_W2t, *p_attn_fb;
    cudaGetSymbolAddress((void**)&p_qln,  g_qln);
    cudaGetSymbolAddress((void**)&p_kvln, g_kvln);
    cudaGetSymbolAddress((void**)&p_Qh,   g_Qh);
    cudaGetSymbolAddress((void**)&p_Kh,   g_Kh);
    cudaGetSymbolAddress((void**)&p_Vt,   g_Vt);
    cudaGetSymbolAddress((void**)&p_ctx,  g_ctx);
    cudaGetSymbolAddress((void**)&p_x,    g_x);
    cudaGetSymbolAddress((void**)&p_y,    g_y);
    cudaGetSymbolAddress((void**)&p_h,    g_h);
    cudaGetSymbolAddress((void**)&p_Wqt,  g_Wqt);
    cudaGetSymbolAddress((void**)&p_Wkt,  g_Wkt);
    cudaGetSymbolAddress((void**)&p_Wvt,  g_Wvt);
    cudaGetSymbolAddress((void**)&p_Wot,  g_Wot);
    cudaGetSymbolAddress((void**)&p_W1t,  g_W1t);
    cudaGetSymbolAddress((void**)&p_W2t,  g_W2t);
    cudaGetSymbolAddress((void**)&p_attn_fb, g_attn_fb);

    float* out = (float*)d_out;
    float* attn = ((size_t)out_size >= OUT_ELEMS + ATTN_ELEMS) ? (out + OUT_ELEMS)
                                                               : p_attn_fb;

    // 0. weight transposes (NT layout)
    transpose_kernel<<<dim3(32, 32), 256>>>(Wq, p_Wqt, DMODEL, DMODEL);
    transpose_kernel<<<dim3(32, 32), 256>>>(Wk, p_Wkt, DMODEL, DMODEL);
    transpose_kernel<<<dim3(32, 32), 256>>>(Wv, p_Wvt, DMODEL, DMODEL);
    transpose_kernel<<<dim3(32, 32), 256>>>(Wo, p_Wot, DMODEL, DMODEL);
    transpose_kernel<<<dim3(128, 32), 256>>>(W1, p_W1t, DMODEL, DFFN);
    transpose_kernel<<<dim3(32, 128), 256>>>(W2, p_W2t, DFFN, DMODEL);

    // 1-2. pre-norms
    ln_kernel<<<KVROWS, 256>>>(memory, g_kv, b_kv, p_kvln);
    ln_kernel<<<QROWS,  256>>>(q,      g_q,  b_q,  p_qln);

    // 3-5. QKV projections (head-split epilogues)
    mma_nt_kernel<128,128,2,4,3><<<dim3(8, 16), 256>>>(p_qln,  p_Wqt, bq, nullptr, p_Qh, QROWS,  DMODEL, DMODEL, 0, 0);
    mma_nt_kernel<128,128,2,4,4><<<dim3(8, 64), 256>>>(p_kvln, p_Wkt, bk, nullptr, p_Kh, KVROWS, DMODEL, DMODEL, 0, 0);
    mma_nt_kernel<128,128,2,4,5><<<dim3(8, 64), 256>>>(p_kvln, p_Wvt, bv, nullptr, p_Vt, KVROWS, DMODEL, DMODEL, 0, 0);

    // 6. scores: per (b,h): [256,1024] = Qh[bh] * Kh[bh]^T, *0.125
    mma_nt_kernel<128,128,2,4,6><<<dim3(8, 2, BBATCH*NHEADS), 256>>>(
        p_Qh, p_Kh, nullptr, nullptr, attn, SQLEN, SKVLEN, DHEAD,
        (long)SQLEN*DHEAD, (long)SKVLEN*DHEAD);

    // 7. softmax in place
    softmax_kernel<<<BBATCH*NHEADS*SQLEN, 256>>>(attn);

    // 8. ctx: per (b,h): [256,64] = attn[bh] * Vt[bh]^T  -> row-major ctx
    mma_nt_kernel<128,64,4,2,7><<<dim3(1, 2, BBATCH*NHEADS), 256>>>(
        attn, p_Vt, nullptr, nullptr, p_ctx, SQLEN, DHEAD, SKVLEN,
        (long)SQLEN*SKVLEN, (long)DHEAD*SKVLEN);

    // 9. x = ctx @ Wo + bo
    mma_nt_kernel<128,128,2,4,0><<<dim3(8, 16), 256>>>(p_ctx, p_Wot, bo, nullptr, p_x, QROWS, DMODEL, DMODEL, 0, 0);

    // 10. y = LN_ff(x)
    ln_kernel<<<QROWS, 256>>>(p_x, g_ff, b_ff, p_y);

    // 11. h = gelu(y @ W1 + b1)
    mma_nt_kernel<128,128,2,4,1><<<dim3(32, 16), 256>>>(p_y, p_W1t, b1, nullptr, p_h, QROWS, DFFN, DMODEL, 0, 0);

    // 12. out = h @ W2 + b2 + x
    mma_nt_kernel<128,128,2,4,2><<<dim3(8, 16), 256>>>(p_h, p_W2t, b2, p_x, out, QROWS, DMODEL, DFFN, 0, 0);
}

// round 5
// speedup vs baseline: 1.5021x; 1.5021x over previous
#include <cuda_runtime.h>
#include <cuda_fp16.h>
#include <math.h>
#include <stdint.h>

#define BBATCH 8
#define SQLEN  256
#define SKVLEN 1024
#define DMODEL 1024
#define NHEADS 16
#define DHEAD  64
#define DFFN   4096
#define QROWS  (BBATCH*SQLEN)
#define KVROWS (BBATCH*SKVLEN)
#define OUT_ELEMS  ((size_t)QROWS*DMODEL)
#define ATTN_ELEMS ((size_t)BBATCH*NHEADS*SQLEN*SKVLEN)

// ----------------------------- scratch (fp16 operands) -------------------
__device__ __half g_qln_h [QROWS*DMODEL];
__device__ __half g_kvln_h[KVROWS*DMODEL];
__device__ __half g_Qh [QROWS*DMODEL];      // [b][h][sq][dk]
__device__ __half g_Kh [KVROWS*DMODEL];     // [b][h][skv][dk]
__device__ __half g_Vt [KVROWS*DMODEL];     // [b][h][dk][skv]
__device__ __half g_attn_h[BBATCH*NHEADS*SQLEN*SKVLEN];
__device__ __half g_ctx_h[QROWS*DMODEL];
__device__ __half g_y_h [QROWS*DMODEL];
__device__ __half g_hh  [QROWS*DFFN];
__device__ __half g_Wqt[DMODEL*DMODEL];
__device__ __half g_Wkt[DMODEL*DMODEL];
__device__ __half g_Wvt[DMODEL*DMODEL];
__device__ __half g_Wot[DMODEL*DMODEL];
__device__ __half g_W1t[DFFN*DMODEL];
__device__ __half g_W2t[DMODEL*DFFN];
__device__ float  g_x [QROWS*DMODEL];       // attn output (fp32, residual + LN input)
__device__ float  g_attn_fb[BBATCH*NHEADS*SQLEN*SKVLEN];

// ----------------------------- transpose -> fp16 -------------------------
__global__ void __launch_bounds__(256) transpose_h_kernel(const float* __restrict__ W,
                                                          __half* __restrict__ Wt,
                                                          int K, int N) {
    __shared__ float t[32][33];
    const int n0 = blockIdx.x * 32, k0 = blockIdx.y * 32;
    const int x = threadIdx.x & 31, y = threadIdx.x >> 5;
    #pragma unroll
    for (int i = 0; i < 32; i += 8)
        t[y + i][x] = W[(size_t)(k0 + y + i) * N + n0 + x];
    __syncthreads();
    #pragma unroll
    for (int i = 0; i < 32; i += 8)
        Wt[(size_t)(n0 + y + i) * K + k0 + x] = __float2half_rn(t[x][y + i]);
}

// ----------------------------- LayerNorm -> fp16 -------------------------
__global__ void __launch_bounds__(256) ln_h_kernel(const float* __restrict__ x,
                                                   const float* __restrict__ g,
                                                   const float* __restrict__ b,
                                                   __half* __restrict__ y) {
    __shared__ float ssum[256], ssq[256];
    const int row = blockIdx.x, tid = threadIdx.x;
    const float4 xv = ((const float4*)(x + (size_t)row*DMODEL))[tid];
    ssum[tid] = xv.x + xv.y + xv.z + xv.w;
    ssq [tid] = xv.x*xv.x + xv.y*xv.y + xv.z*xv.z + xv.w*xv.w;
    __syncthreads();
    for (int st = 128; st > 0; st >>= 1) {
        if (tid < st) { ssum[tid] += ssum[tid+st]; ssq[tid] += ssq[tid+st]; }
        __syncthreads();
    }
    const float mu  = ssum[0] * (1.0f/DMODEL);
    const float inv = rsqrtf(ssq[0]*(1.0f/DMODEL) - mu*mu + 1e-5f);
    const float4 gv = ((const float4*)g)[tid];
    const float4 bv = ((const float4*)b)[tid];
    __half2* o = (__half2*)(y + (size_t)row*DMODEL) + tid*2;
    o[0] = __floats2half2_rn((xv.x - mu)*inv*gv.x + bv.x, (xv.y - mu)*inv*gv.y + bv.y);
    o[1] = __floats2half2_rn((xv.z - mu)*inv*gv.z + bv.z, (xv.w - mu)*inv*gv.w + bv.w);
}

// ---------------- softmax: fp32 in place + fp16 copy ---------------------
__global__ void __launch_bounds__(256) softmax_kernel(float* __restrict__ attn,
                                                      __half* __restrict__ attn_h) {
    __shared__ float red[256];
    const size_t row = blockIdx.x;
    float4* p = (float4*)(attn + row*(size_t)SKVLEN);
    const int tid = threadIdx.x;
    float4 v = p[tid];
    float m = fmaxf(fmaxf(v.x, v.y), fmaxf(v.z, v.w));
    red[tid] = m; __syncthreads();
    for (int st = 128; st > 0; st >>= 1) { if (tid < st) red[tid] = fmaxf(red[tid], red[tid+st]); __syncthreads(); }
    m = red[0]; __syncthreads();
    v.x = __expf(v.x - m); v.y = __expf(v.y - m); v.z = __expf(v.z - m); v.w = __expf(v.w - m);
    red[tid] = v.x + v.y + v.z + v.w; __syncthreads();
    for (int st = 128; st > 0; st >>= 1) { if (tid < st) red[tid] += red[tid+st]; __syncthreads(); }
    const float inv = 1.0f / red[0];
    v.x *= inv; v.y *= inv; v.z *= inv; v.w *= inv;
    p[tid] = v;
    __half2* ph = (__half2*)(attn_h + row*(size_t)SKVLEN) + tid*2;
    ph[0] = __floats2half2_rn(v.x, v.y);
    ph[1] = __floats2half2_rn(v.z, v.w);
}

// ----------------------------- fp16 MMA helpers --------------------------
__device__ __forceinline__ void ldsm4(uint32_t (&d)[4], uint32_t addr) {
    asm volatile("ldmatrix.sync.aligned.m8n8.x4.shared.b16 {%0,%1,%2,%3}, [%4];"
        : "=r"(d[0]), "=r"(d[1]), "=r"(d[2]), "=r"(d[3]) : "r"(addr));
}
__device__ __forceinline__ void mma_f16(float (&c)[4], const uint32_t (&a)[4],
                                        const uint32_t (&b)[2]) {
    asm volatile("mma.sync.aligned.m16n8k16.row.col.f32.f16.f16.f32 "
        "{%0,%1,%2,%3},{%4,%5,%6,%7},{%8,%9},{%0,%1,%2,%3};"
        : "+f"(c[0]), "+f"(c[1]), "+f"(c[2]), "+f"(c[3])
        : "r"(a[0]), "r"(a[1]), "r"(a[2]), "r"(a[3]), "r"(b[0]), "r"(b[1]));
}

// Epilogue modes:
// 0: fp32 x = v+bias            1: fp16 gelu(v+bias)        2: fp32 out = v+bias+res
// 3: fp16 Qh split              4: fp16 Kh split            5: fp16 Vt split-transposed
// 6: fp32 attn logits * 0.125   7: fp16 ctx row-major
template<int MODE>
__device__ __forceinline__ void store_elem(void* __restrict__ Cv,
                                           const float* __restrict__ bias,
                                           const float* __restrict__ res,
                                           int N, int bz, int row, int col, float v) {
    if (MODE == 0) {
        ((float*)Cv)[(size_t)row*N + col] = v + bias[col];
    } else if (MODE == 1) {
        float x = v + bias[col];
        ((__half*)Cv)[(size_t)row*N + col] =
            __float2half_rn(0.5f*x*(1.0f + erff(x*0.70710678118654752f)));
    } else if (MODE == 2) {
        ((float*)Cv)[(size_t)row*N + col] = v + bias[col] + res[(size_t)row*N + col];
    } else if (MODE == 3) {
        ((__half*)Cv)[(size_t)(row>>8)*(NHEADS*SQLEN*DHEAD) + (size_t)(col>>6)*(SQLEN*DHEAD)
          + (size_t)(row&255)*DHEAD + (col&63)] = __float2half_rn(v + bias[col]);
    } else if (MODE == 4) {
        ((__half*)Cv)[(size_t)(row>>10)*(NHEADS*SKVLEN*DHEAD) + (size_t)(col>>6)*(SKVLEN*DHEAD)
          + (size_t)(row&1023)*DHEAD + (col&63)] = __float2half_rn(v + bias[col]);
    } else if (MODE == 5) {
        ((__half*)Cv)[(size_t)(row>>10)*(NHEADS*DHEAD*SKVLEN) + (size_t)(col>>6)*(DHEAD*SKVLEN)
          + (size_t)(col&63)*SKVLEN + (row&1023)] = __float2half_rn(v + bias[col]);
    } else if (MODE == 6) {
        ((float*)Cv)[(size_t)bz*(SQLEN*SKVLEN) + (size_t)row*SKVLEN + col] = v * 0.125f;
    } else if (MODE == 7) {
        ((__half*)Cv)[((size_t)(bz>>4)*SQLEN + row)*DMODEL + (size_t)(bz&15)*DHEAD + col] =
            __float2half_rn(v);
    }
}

// ---------- fp16 NT GEMM: C = A[M,K] * B[N,K]^T, BK=32, 2-stage ----------
template<int BM, int BN, int WM, int WN, int MODE>
__global__ void __launch_bounds__(256, 2) hgemm_nt(
    const __half* __restrict__ Ag, const __half* __restrict__ Bg,
    const float* __restrict__ bias, const float* __restrict__ res,
    void* __restrict__ Cg, int N, int K, long sA, long sB)
{
    constexpr int AST = 40;                  // 32 + 8 halves pad (80B rows, 5x16B: conflict-free)
    constexpr int MT = BM / (WM * 16);
    constexpr int NT = BN / (WN * 8);
    __shared__ __align__(16) __half As[2][BM][AST];
    __shared__ __align__(16) __half Bs[2][BN][AST];

    const int tid  = threadIdx.x;
    const int warp = tid >> 5, lane = tid & 31;
    const int wm0 = (warp % WM) * (BM / WM);
    const int wn0 = (warp / WM) * (BN / WN);
    const int bm0 = blockIdx.y * BM;
    const int bn0 = blockIdx.x * BN;
    const int bz  = blockIdx.z;
    const __half* A = Ag + (size_t)bz * sA + (size_t)bm0 * K;
    const __half* B = Bg + (size_t)bz * sB + (size_t)bn0 * K;

    const uint32_t sA32 = (uint32_t)__cvta_generic_to_shared(&As[0][0][0]);
    const uint32_t sB32 = (uint32_t)__cvta_generic_to_shared(&Bs[0][0][0]);

    float acc[MT][NT][4];
    #pragma unroll
    for (int i = 0; i < MT; ++i)
        #pragma unroll
        for (int j = 0; j < NT; ++j)
            { acc[i][j][0]=0.f; acc[i][j][1]=0.f; acc[i][j][2]=0.f; acc[i][j][3]=0.f; }

    const int KT = K >> 5;

    auto prefetch = [&](int buf, int kt) {
        const __half* Ak = A + kt * 32;
        #pragma unroll
        for (int i = tid; i < BM*4; i += 256) {
            const int r = i >> 2, c = i & 3;
            uint32_t dst = sA32 + (uint32_t)(((buf*BM + r)*AST + c*8) * 2);
            asm volatile("cp.async.cg.shared.global [%0], [%1], 16;"
                         :: "r"(dst), "l"(Ak + (size_t)r*K + c*8));
        }
        const __half* Bk = B + kt * 32;
        #pragma unroll
        for (int i = tid; i < BN*4; i += 256) {
            const int r = i >> 2, c = i & 3;
            uint32_t dst = sB32 + (uint32_t)(((buf*BN + r)*AST + c*8) * 2);
            asm volatile("cp.async.cg.shared.global [%0], [%1], 16;"
                         :: "r"(dst), "l"(Bk + (size_t)r*K + c*8));
        }
        asm volatile("cp.async.commit_group;" ::: "memory");
    };

    prefetch(0, 0);

    for (int kt = 0; kt < KT; ++kt) {
        const int buf = kt & 1;
        if (kt + 1 < KT) {
            prefetch(buf ^ 1, kt + 1);
            asm volatile("cp.async.wait_group 1;" ::: "memory");
        } else {
            asm volatile("cp.async.wait_group 0;" ::: "memory");
        }
        __syncthreads();

        #pragma unroll
        for (int ks = 0; ks < 2; ++ks) {
            uint32_t af[MT][4];
            uint32_t bf[NT][2];
            const int lr = lane & 15;
            const int lc = (lane >> 4) * 8 + ks * 16;
            #pragma unroll
            for (int mt = 0; mt < MT; ++mt) {
                uint32_t addr = sA32 + (uint32_t)((((buf*BM) + wm0 + mt*16 + lr)*AST + lc) * 2);
                ldsm4(af[mt], addr);
            }
            #pragma unroll
            for (int nt2 = 0; nt2 < NT/2; ++nt2) {
                uint32_t d[4];
                uint32_t addr = sB32 + (uint32_t)((((buf*BN) + wn0 + nt2*16 + lr)*AST + lc) * 2);
                ldsm4(d, addr);
                bf[nt2*2  ][0] = d[0]; bf[nt2*2  ][1] = d[2];
                bf[nt2*2+1][0] = d[1]; bf[nt2*2+1][1] = d[3];
            }
            #pragma unroll
            for (int mt = 0; mt < MT; ++mt)
                #pragma unroll
                for (int nt = 0; nt < NT; ++nt)
                    mma_f16(acc[mt][nt], af[mt], bf[nt]);
        }
        __syncthreads();
    }

    const int g = lane >> 2, t = lane & 3;
    #pragma unroll
    for (int mt = 0; mt < MT; ++mt) {
        #pragma unroll
        for (int nt = 0; nt < NT; ++nt) {
            const int r0 = bm0 + wm0 + mt*16 + g;
            const int c0 = bn0 + wn0 + nt*8 + t*2;
            store_elem<MODE>(Cg, bias, res, N, bz, r0,     c0,     acc[mt][nt][0]);
            store_elem<MODE>(Cg, bias, res, N, bz, r0,     c0 + 1, acc[mt][nt][1]);
            store_elem<MODE>(Cg, bias, res, N, bz, r0 + 8, c0,     acc[mt][nt][2]);
            store_elem<MODE>(Cg, bias, res, N, bz, r0 + 8, c0 + 1, acc[mt][nt][3]);
        }
    }
}

// ----------------------------- launch ------------------------------------
extern "C" void kernel_launch(void* const* d_in, const int* in_sizes, int n_in,
                              void* d_out, int out_size) {
    const float* memory = (const float*)d_in[0];
    const float* q      = (const float*)d_in[1];
    const float* Wq = (const float*)d_in[2];  const float* bq = (const float*)d_in[3];
    const float* Wk = (const float*)d_in[4];  const float* bk = (const float*)d_in[5];
    const float* Wv = (const float*)d_in[6];  const float* bv = (const float*)d_in[7];
    const float* Wo = (const float*)d_in[8];  const float* bo = (const float*)d_in[9];
    const float* g_kv = (const float*)d_in[10]; const float* b_kv = (const float*)d_in[11];
    const float* g_q  = (const float*)d_in[12]; const float* b_q  = (const float*)d_in[13];
    const float* g_ff = (const float*)d_in[14]; const float* b_ff = (const float*)d_in[15];
    const float* W1 = (const float*)d_in[16]; const float* b1 = (const float*)d_in[17];
    const float* W2 = (const float*)d_in[18]; const float* b2 = (const float*)d_in[19];

    __half *p_qln, *p_kvln, *p_Qh, *p_Kh, *p_Vt, *p_attn_h, *p_ctx, *p_y, *p_h;
    __half *p_Wqt, *p_Wkt, *p_Wvt, *p_Wot, *p_W1t, *p_W2t;
    float *p_x, *p_fb;
    cudaGetSymbolAddress((void**)&p_qln,  g_qln_h);
    cudaGetSymbolAddress((void**)&p_kvln, g_kvln_h);
    cudaGetSymbolAddress((void**)&p_Qh,   g_Qh);
    cudaGetSymbolAddress((void**)&p_Kh,   g_Kh);
    cudaGetSymbolAddress((void**)&p_Vt,   g_Vt);
    cudaGetSymbolAddress((void**)&p_attn_h, g_attn_h);
    cudaGetSymbolAddress((void**)&p_ctx,  g_ctx_h);
    cudaGetSymbolAddress((void**)&p_y,    g_y_h);
    cudaGetSymbolAddress((void**)&p_h,    g_hh);
    cudaGetSymbolAddress((void**)&p_Wqt,  g_Wqt);
    cudaGetSymbolAddress((void**)&p_Wkt,  g_Wkt);
    cudaGetSymbolAddress((void**)&p_Wvt,  g_Wvt);
    cudaGetSymbolAddress((void**)&p_Wot,  g_Wot);
    cudaGetSymbolAddress((void**)&p_W1t,  g_W1t);
    cudaGetSymbolAddress((void**)&p_W2t,  g_W2t);
    cudaGetSymbolAddress((void**)&p_x,    g_x);
    cudaGetSymbolAddress((void**)&p_fb,   g_attn_fb);

    float* out = (float*)d_out;
    float* attn = ((size_t)out_size >= OUT_ELEMS + ATTN_ELEMS) ? (out + OUT_ELEMS) : p_fb;

    // 0. weight transposes -> fp16 NT layout
    transpose_h_kernel<<<dim3(32, 32), 256>>>(Wq, p_Wqt, DMODEL, DMODEL);
    transpose_h_kernel<<<dim3(32, 32), 256>>>(Wk, p_Wkt, DMODEL, DMODEL);
    transpose_h_kernel<<<dim3(32, 32), 256>>>(Wv, p_Wvt, DMODEL, DMODEL);
    transpose_h_kernel<<<dim3(32, 32), 256>>>(Wo, p_Wot, DMODEL, DMODEL);
    transpose_h_kernel<<<dim3(128, 32), 256>>>(W1, p_W1t, DMODEL, DFFN);
    transpose_h_kernel<<<dim3(32, 128), 256>>>(W2, p_W2t, DFFN, DMODEL);

    // 1-2. pre-norms -> fp16
    ln_h_kernel<<<KVROWS, 256>>>(memory, g_kv, b_kv, p_kvln);
    ln_h_kernel<<<QROWS,  256>>>(q,      g_q,  b_q,  p_qln);

    // 3-5. QKV projections (head-split epilogues, fp16 out)
    hgemm_nt<128,128,2,4,3><<<dim3(8, 16), 256>>>(p_qln,  p_Wqt, bq, nullptr, p_Qh, DMODEL, DMODEL, 0, 0);
    hgemm_nt<128,128,2,4,4><<<dim3(8, 64), 256>>>(p_kvln, p_Wkt, bk, nullptr, p_Kh, DMODEL, DMODEL, 0, 0);
    hgemm_nt<128,128,2,4,5><<<dim3(8, 64), 256>>>(p_kvln, p_Wvt, bv, nullptr, p_Vt, DMODEL, DMODEL, 0, 0);

    // 6. scores: per (b,h): [256,1024] = Qh * Kh^T, *0.125 -> fp32 attn region
    hgemm_nt<128,128,2,4,6><<<dim3(8, 2, BBATCH*NHEADS), 256>>>(
        p_Qh, p_Kh, nullptr, nullptr, attn, SKVLEN, DHEAD,
        (long)SQLEN*DHEAD, (long)SKVLEN*DHEAD);

    // 7. softmax in place (fp32) + fp16 copy for ctx GEMM
    softmax_kernel<<<BBATCH*NHEADS*SQLEN, 256>>>(attn, p_attn_h);

    // 8. ctx: per (b,h): [256,64] = attn_h * Vt^T -> fp16 row-major ctx
    hgemm_nt<128,64,4,2,7><<<dim3(1, 2, BBATCH*NHEADS), 256>>>(
        p_attn_h, p_Vt, nullptr, nullptr, p_ctx, DHEAD, SKVLEN,
        (long)SQLEN*SKVLEN, (long)DHEAD*SKVLEN);

    // 9. x = ctx @ Wo + bo (fp32 out)
    hgemm_nt<128,128,2,4,0><<<dim3(8, 16), 256>>>(p_ctx, p_Wot, bo, nullptr, p_x, DMODEL, DMODEL, 0, 0);

    // 10. y = LN_ff(x) -> fp16
    ln_h_kernel<<<QROWS, 256>>>(p_x, g_ff, b_ff, p_y);

    // 11. h = gelu(y @ W1 + b1) -> fp16
    hgemm_nt<128,128,2,4,1><<<dim3(32, 16), 256>>>(p_y, p_W1t, b1, nullptr, p_h, DFFN, DMODEL, 0, 0);

    // 12. out = h @ W2 + b2 + x (fp32)
    hgemm_nt<128,128,2,4,2><<<dim3(8, 16), 256>>>(p_h, p_W2t, b2, p_x, out, DMODEL, DFFN, 0, 0);
}

// round 6
// speedup vs baseline: 1.6097x; 1.0716x over previous
#include <cuda_runtime.h>
#include <cuda_fp16.h>
#include <math.h>
#include <stdint.h>

#define BBATCH 8
#define SQLEN  256
#define SKVLEN 1024
#define DMODEL 1024
#define NHEADS 16
#define DHEAD  64
#define DFFN   4096
#define QROWS  (BBATCH*SQLEN)
#define KVROWS (BBATCH*SKVLEN)
#define OUT_ELEMS  ((size_t)QROWS*DMODEL)
#define ATTN_ELEMS ((size_t)BBATCH*NHEADS*SQLEN*SKVLEN)

// ----------------------------- scratch -----------------------------------
__device__ __half g_qln_h [QROWS*DMODEL];
__device__ __half g_kvln_h[KVROWS*DMODEL];
__device__ __half g_Qh [QROWS*DMODEL];
__device__ __half g_Kh [KVROWS*DMODEL];
__device__ __half g_Vt [KVROWS*DMODEL];
__device__ __half g_attn_h[BBATCH*NHEADS*SQLEN*SKVLEN];
__device__ __half g_ctx_h[QROWS*DMODEL];
__device__ __half g_y_h [QROWS*DMODEL];
__device__ __half g_hh  [QROWS*DFFN];
__device__ __half g_Wqt[DMODEL*DMODEL];
__device__ __half g_Wkt[DMODEL*DMODEL];
__device__ __half g_Wvt[DMODEL*DMODEL];
__device__ __half g_Wot[DMODEL*DMODEL];
__device__ __half g_W1t[DFFN*DMODEL];
__device__ __half g_W2t[DMODEL*DFFN];
__device__ float  g_x [QROWS*DMODEL];
__device__ float  g_attn_fb[BBATCH*NHEADS*SQLEN*SKVLEN];

// ------------------ fused transposes: all 6 weights in one launch --------
// segments: [0,1024)x4: Wq,Wk,Wv,Wo (1024x1024, 32x32 tiles)
//           [4096,8192): W1 (K=1024,N=4096, tilesX=128)
//           [8192,12288): W2 (K=4096,N=1024, tilesX=32)
__global__ void __launch_bounds__(256) transpose_all_kernel(
    const float* __restrict__ Wq, const float* __restrict__ Wk,
    const float* __restrict__ Wv, const float* __restrict__ Wo,
    const float* __restrict__ W1, const float* __restrict__ W2,
    __half* __restrict__ Wqt, __half* __restrict__ Wkt,
    __half* __restrict__ Wvt, __half* __restrict__ Wot,
    __half* __restrict__ W1t, __half* __restrict__ W2t)
{
    __shared__ float t[32][33];
    const int id = blockIdx.x;
    const float* W; __half* Wt; int K, N, local, tilesX;
    if (id < 4096) {
        K = DMODEL; N = DMODEL; tilesX = 32; local = id & 1023;
        const int w = id >> 10;
        W  = (w == 0) ? Wq  : (w == 1) ? Wk  : (w == 2) ? Wv  : Wo;
        Wt = (w == 0) ? Wqt : (w == 1) ? Wkt : (w == 2) ? Wvt : Wot;
    } else if (id < 8192) {
        K = DMODEL; N = DFFN; tilesX = 128; local = id - 4096; W = W1; Wt = W1t;
    } else {
        K = DFFN; N = DMODEL; tilesX = 32; local = id - 8192; W = W2; Wt = W2t;
    }
    const int n0 = (local % tilesX) * 32, k0 = (local / tilesX) * 32;
    const int x = threadIdx.x & 31, y = threadIdx.x >> 5;
    #pragma unroll
    for (int i = 0; i < 32; i += 8)
        t[y + i][x] = W[(size_t)(k0 + y + i) * N + n0 + x];
    __syncthreads();
    #pragma unroll
    for (int i = 0; i < 32; i += 8)
        Wt[(size_t)(n0 + y + i) * K + k0 + x] = __float2half_rn(t[x][y + i]);
}

// ----------------------------- LayerNorm -> fp16 -------------------------
__global__ void __launch_bounds__(256) ln_h_kernel(const float* __restrict__ x,
                                                   const float* __restrict__ g,
                                                   const float* __restrict__ b,
                                                   __half* __restrict__ y) {
    __shared__ float ssum[256], ssq[256];
    const int row = blockIdx.x, tid = threadIdx.x;
    const float4 xv = ((const float4*)(x + (size_t)row*DMODEL))[tid];
    ssum[tid] = xv.x + xv.y + xv.z + xv.w;
    ssq [tid] = xv.x*xv.x + xv.y*xv.y + xv.z*xv.z + xv.w*xv.w;
    __syncthreads();
    for (int st = 128; st > 0; st >>= 1) {
        if (tid < st) { ssum[tid] += ssum[tid+st]; ssq[tid] += ssq[tid+st]; }
        __syncthreads();
    }
    const float mu  = ssum[0] * (1.0f/DMODEL);
    const float inv = rsqrtf(ssq[0]*(1.0f/DMODEL) - mu*mu + 1e-5f);
    const float4 gv = ((const float4*)g)[tid];
    const float4 bv = ((const float4*)b)[tid];
    __half2* o = (__half2*)(y + (size_t)row*DMODEL) + tid*2;
    o[0] = __floats2half2_rn((xv.x - mu)*inv*gv.x + bv.x, (xv.y - mu)*inv*gv.y + bv.y);
    o[1] = __floats2half2_rn((xv.z - mu)*inv*gv.z + bv.z, (xv.w - mu)*inv*gv.w + bv.w);
}

// ---------------- softmax: fp32 in place + fp16 copy ---------------------
__global__ void __launch_bounds__(256) softmax_kernel(float* __restrict__ attn,
                                                      __half* __restrict__ attn_h) {
    __shared__ float red[256];
    const size_t row = blockIdx.x;
    float4* p = (float4*)(attn + row*(size_t)SKVLEN);
    const int tid = threadIdx.x;
    float4 v = p[tid];
    float m = fmaxf(fmaxf(v.x, v.y), fmaxf(v.z, v.w));
    red[tid] = m; __syncthreads();
    for (int st = 128; st > 0; st >>= 1) { if (tid < st) red[tid] = fmaxf(red[tid], red[tid+st]); __syncthreads(); }
    m = red[0]; __syncthreads();
    v.x = __expf(v.x - m); v.y = __expf(v.y - m); v.z = __expf(v.z - m); v.w = __expf(v.w - m);
    red[tid] = v.x + v.y + v.z + v.w; __syncthreads();
    for (int st = 128; st > 0; st >>= 1) { if (tid < st) red[tid] += red[tid+st]; __syncthreads(); }
    const float inv = 1.0f / red[0];
    v.x *= inv; v.y *= inv; v.z *= inv; v.w *= inv;
    p[tid] = v;
    __half2* ph = (__half2*)(attn_h + row*(size_t)SKVLEN) + tid*2;
    ph[0] = __floats2half2_rn(v.x, v.y);
    ph[1] = __floats2half2_rn(v.z, v.w);
}

// ----------------------------- fp16 MMA helpers --------------------------
__device__ __forceinline__ void ldsm4(uint32_t (&d)[4], uint32_t addr) {
    asm volatile("ldmatrix.sync.aligned.m8n8.x4.shared.b16 {%0,%1,%2,%3}, [%4];"
        : "=r"(d[0]), "=r"(d[1]), "=r"(d[2]), "=r"(d[3]) : "r"(addr));
}
__device__ __forceinline__ void mma_f16(float (&c)[4], const uint32_t (&a)[4],
                                        const uint32_t (&b)[2]) {
    asm volatile("mma.sync.aligned.m16n8k16.row.col.f32.f16.f16.f32 "
        "{%0,%1,%2,%3},{%4,%5,%6,%7},{%8,%9},{%0,%1,%2,%3};"
        : "+f"(c[0]), "+f"(c[1]), "+f"(c[2]), "+f"(c[3])
        : "r"(a[0]), "r"(a[1]), "r"(a[2]), "r"(a[3]), "r"(b[0]), "r"(b[1]));
}

// Epilogue modes (same as Round 5)
template<int MODE>
__device__ __forceinline__ void store_elem(void* __restrict__ Cv,
                                           const float* __restrict__ bias,
                                           const float* __restrict__ res,
                                           int N, int bz, int row, int col, float v) {
    if (MODE == 0) {
        ((float*)Cv)[(size_t)row*N + col] = v + bias[col];
    } else if (MODE == 1) {
        float x = v + bias[col];
        ((__half*)Cv)[(size_t)row*N + col] =
            __float2half_rn(0.5f*x*(1.0f + erff(x*0.70710678118654752f)));
    } else if (MODE == 2) {
        ((float*)Cv)[(size_t)row*N + col] = v + bias[col] + res[(size_t)row*N + col];
    } else if (MODE == 3) {
        ((__half*)Cv)[(size_t)(row>>8)*(NHEADS*SQLEN*DHEAD) + (size_t)(col>>6)*(SQLEN*DHEAD)
          + (size_t)(row&255)*DHEAD + (col&63)] = __float2half_rn(v + bias[col]);
    } else if (MODE == 4) {
        ((__half*)Cv)[(size_t)(row>>10)*(NHEADS*SKVLEN*DHEAD) + (size_t)(col>>6)*(SKVLEN*DHEAD)
          + (size_t)(row&1023)*DHEAD + (col&63)] = __float2half_rn(v + bias[col]);
    } else if (MODE == 5) {
        ((__half*)Cv)[(size_t)(row>>10)*(NHEADS*DHEAD*SKVLEN) + (size_t)(col>>6)*(DHEAD*SKVLEN)
          + (size_t)(col&63)*SKVLEN + (row&1023)] = __float2half_rn(v + bias[col]);
    } else if (MODE == 6) {
        ((float*)Cv)[(size_t)bz*(SQLEN*SKVLEN) + (size_t)row*SKVLEN + col] = v * 0.125f;
    } else if (MODE == 7) {
        ((__half*)Cv)[((size_t)(bz>>4)*SQLEN + row)*DMODEL + (size_t)(bz&15)*DHEAD + col] =
            __float2half_rn(v);
    }
}

// ---- fp16 NT GEMM: C = A[M,K] * B[N,K]^T, BK=32, STAGES-deep pipeline ----
// dynamic smem: STAGES stages of [A: BM x 40 halves][B: BN x 40 halves]
template<int BM, int BN, int WM, int WN, int STAGES, int MODE>
__global__ void __launch_bounds__(256, 2) hgemm_nt(
    const __half* __restrict__ Ag, const __half* __restrict__ Bg,
    const float* __restrict__ bias, const float* __restrict__ res,
    void* __restrict__ Cg, int N, int K, long sA, long sB)
{
    constexpr int ROWB = 80;                       // 40 halves (32 + 8 pad)
    constexpr int STGB = (BM + BN) * ROWB;         // bytes per stage
    constexpr int MT = BM / (WM * 16);
    constexpr int NT = BN / (WN * 8);
    extern __shared__ __align__(16) __half dynsm[];
    const uint32_t sm0 = (uint32_t)__cvta_generic_to_shared(dynsm);

    const int tid  = threadIdx.x;
    const int warp = tid >> 5, lane = tid & 31;
    const int wm0 = (warp % WM) * (BM / WM);
    const int wn0 = (warp / WM) * (BN / WN);
    const int bm0 = blockIdx.y * BM;
    const int bn0 = blockIdx.x * BN;
    const int bz  = blockIdx.z;
    const __half* A = Ag + (size_t)bz * sA + (size_t)bm0 * K;
    const __half* B = Bg + (size_t)bz * sB + (size_t)bn0 * K;

    float acc[MT][NT][4];
    #pragma unroll
    for (int i = 0; i < MT; ++i)
        #pragma unroll
        for (int j = 0; j < NT; ++j)
            { acc[i][j][0]=0.f; acc[i][j][1]=0.f; acc[i][j][2]=0.f; acc[i][j][3]=0.f; }

    const int KT = K >> 5;

    auto prefetch = [&](int it) {
        if (it < KT) {
            const uint32_t sb = sm0 + (uint32_t)(it % STAGES) * STGB;
            const __half* Ak = A + it * 32;
            const __half* Bk = B + it * 32;
            #pragma unroll
            for (int i = tid; i < (BM + BN) * 4; i += 256) {
                const int r = i >> 2, c = i & 3;
                uint32_t dst; const __half* src;
                if (r < BM) { dst = sb + (uint32_t)(r*ROWB + c*16); src = Ak + (size_t)r*K + c*8; }
                else { dst = sb + (uint32_t)(BM*ROWB + (r-BM)*ROWB + c*16);
                       src = Bk + (size_t)(r-BM)*K + c*8; }
                asm volatile("cp.async.cg.shared.global [%0], [%1], 16;" :: "r"(dst), "l"(src));
            }
        }
        asm volatile("cp.async.commit_group;" ::: "memory");
    };

    #pragma unroll
    for (int p = 0; p < STAGES - 1; ++p) prefetch(p);

    for (int kt = 0; kt < KT; ++kt) {
        asm volatile("cp.async.wait_group %0;" :: "n"(STAGES - 2) : "memory");
        __syncthreads();
        prefetch(kt + STAGES - 1);

        const uint32_t sbA = sm0 + (uint32_t)(kt % STAGES) * STGB;
        const uint32_t sbB = sbA + BM * ROWB;
        #pragma unroll
        for (int ks = 0; ks < 2; ++ks) {
            uint32_t af[MT][4];
            uint32_t bf[NT][2];
            const int lr  = lane & 15;
            const int lcb = ((lane >> 4) * 8 + ks * 16) * 2;   // byte offset in row
            #pragma unroll
            for (int mt = 0; mt < MT; ++mt)
                ldsm4(af[mt], sbA + (uint32_t)((wm0 + mt*16 + lr)*ROWB + lcb));
            #pragma unroll
            for (int nt2 = 0; nt2 < NT/2; ++nt2) {
                uint32_t d[4];
                ldsm4(d, sbB + (uint32_t)((wn0 + nt2*16 + lr)*ROWB + lcb));
                bf[nt2*2  ][0] = d[0]; bf[nt2*2  ][1] = d[2];
                bf[nt2*2+1][0] = d[1]; bf[nt2*2+1][1] = d[3];
            }
            #pragma unroll
            for (int mt = 0; mt < MT; ++mt)
                #pragma unroll
                for (int nt = 0; nt < NT; ++nt)
                    mma_f16(acc[mt][nt], af[mt], bf[nt]);
        }
    }

    const int g = lane >> 2, t = lane & 3;
    #pragma unroll
    for (int mt = 0; mt < MT; ++mt) {
        #pragma unroll
        for (int nt = 0; nt < NT; ++nt) {
            const int r0 = bm0 + wm0 + mt*16 + g;
            const int c0 = bn0 + wn0 + nt*8 + t*2;
            store_elem<MODE>(Cg, bias, res, N, bz, r0,     c0,     acc[mt][nt][0]);
            store_elem<MODE>(Cg, bias, res, N, bz, r0,     c0 + 1, acc[mt][nt][1]);
            store_elem<MODE>(Cg, bias, res, N, bz, r0 + 8, c0,     acc[mt][nt][2]);
            store_elem<MODE>(Cg, bias, res, N, bz, r0 + 8, c0 + 1, acc[mt][nt][3]);
        }
    }
}

// ----------------------------- launch ------------------------------------
#define SMEMB(BM, BN, S) ((S) * ((BM) + (BN)) * 80)

extern "C" void kernel_launch(void* const* d_in, const int* in_sizes, int n_in,
                              void* d_out, int out_size) {
    const float* memory = (const float*)d_in[0];
    const float* q      = (const float*)d_in[1];
    const float* Wq = (const float*)d_in[2];  const float* bq = (const float*)d_in[3];
    const float* Wk = (const float*)d_in[4];  const float* bk = (const float*)d_in[5];
    const float* Wv = (const float*)d_in[6];  const float* bv = (const float*)d_in[7];
    const float* Wo = (const float*)d_in[8];  const float* bo = (const float*)d_in[9];
    const float* g_kv = (const float*)d_in[10]; const float* b_kv = (const float*)d_in[11];
    const float* g_q  = (const float*)d_in[12]; const float* b_q  = (const float*)d_in[13];
    const float* g_ff = (const float*)d_in[14]; const float* b_ff = (const float*)d_in[15];
    const float* W1 = (const float*)d_in[16]; const float* b1 = (const float*)d_in[17];
    const float* W2 = (const float*)d_in[18]; const float* b2 = (const float*)d_in[19];

    __half *p_qln, *p_kvln, *p_Qh, *p_Kh, *p_Vt, *p_attn_h, *p_ctx, *p_y, *p_h;
    __half *p_Wqt, *p_Wkt, *p_Wvt, *p_Wot, *p_W1t, *p_W2t;
    float *p_x, *p_fb;
    cudaGetSymbolAddress((void**)&p_qln,  g_qln_h);
    cudaGetSymbolAddress((void**)&p_kvln, g_kvln_h);
    cudaGetSymbolAddress((void**)&p_Qh,   g_Qh);
    cudaGetSymbolAddress((void**)&p_Kh,   g_Kh);
    cudaGetSymbolAddress((void**)&p_Vt,   g_Vt);
    cudaGetSymbolAddress((void**)&p_attn_h, g_attn_h);
    cudaGetSymbolAddress((void**)&p_ctx,  g_ctx_h);
    cudaGetSymbolAddress((void**)&p_y,    g_y_h);
    cudaGetSymbolAddress((void**)&p_h,    g_hh);
    cudaGetSymbolAddress((void**)&p_Wqt,  g_Wqt);
    cudaGetSymbolAddress((void**)&p_Wkt,  g_Wkt);
    cudaGetSymbolAddress((void**)&p_Wvt,  g_Wvt);
    cudaGetSymbolAddress((void**)&p_Wot,  g_Wot);
    cudaGetSymbolAddress((void**)&p_W1t,  g_W1t);
    cudaGetSymbolAddress((void**)&p_W2t,  g_W2t);
    cudaGetSymbolAddress((void**)&p_x,    g_x);
    cudaGetSymbolAddress((void**)&p_fb,   g_attn_fb);

    float* out = (float*)d_out;
    float* attn = ((size_t)out_size >= OUT_ELEMS + ATTN_ELEMS) ? (out + OUT_ELEMS) : p_fb;

    // opt-in smem limits (idempotent)
    cudaFuncSetAttribute(hgemm_nt<64,128,2,4,4,3>,  cudaFuncAttributeMaxDynamicSharedMemorySize, SMEMB(64,128,4));
    cudaFuncSetAttribute(hgemm_nt<128,128,2,4,4,4>, cudaFuncAttributeMaxDynamicSharedMemorySize, SMEMB(128,128,4));
    cudaFuncSetAttribute(hgemm_nt<128,128,2,4,4,5>, cudaFuncAttributeMaxDynamicSharedMemorySize, SMEMB(128,128,4));
    cudaFuncSetAttribute(hgemm_nt<128,128,2,4,4,6>, cudaFuncAttributeMaxDynamicSharedMemorySize, SMEMB(128,128,4));
    cudaFuncSetAttribute(hgemm_nt<128,64,4,2,4,7>,  cudaFuncAttributeMaxDynamicSharedMemorySize, SMEMB(128,64,4));
    cudaFuncSetAttribute(hgemm_nt<64,128,2,4,4,0>,  cudaFuncAttributeMaxDynamicSharedMemorySize, SMEMB(64,128,4));
    cudaFuncSetAttribute(hgemm_nt<128,128,2,4,4,1>, cudaFuncAttributeMaxDynamicSharedMemorySize, SMEMB(128,128,4));
    cudaFuncSetAttribute(hgemm_nt<64,128,2,4,4,2>,  cudaFuncAttributeMaxDynamicSharedMemorySize, SMEMB(64,128,4));

    // 0. all weight transposes in one launch
    transpose_all_kernel<<<12288, 256>>>(Wq, Wk, Wv, Wo, W1, W2,
                                         p_Wqt, p_Wkt, p_Wvt, p_Wot, p_W1t, p_W2t);

    // 1-2. pre-norms -> fp16
    ln_h_kernel<<<KVROWS, 256>>>(memory, g_kv, b_kv, p_kvln);
    ln_h_kernel<<<QROWS,  256>>>(q,      g_q,  b_q,  p_qln);

    // 3-5. QKV projections
    hgemm_nt<64,128,2,4,4,3><<<dim3(8, 32), 256, SMEMB(64,128,4)>>>(
        p_qln,  p_Wqt, bq, nullptr, p_Qh, DMODEL, DMODEL, 0, 0);
    hgemm_nt<128,128,2,4,4,4><<<dim3(8, 64), 256, SMEMB(128,128,4)>>>(
        p_kvln, p_Wkt, bk, nullptr, p_Kh, DMODEL, DMODEL, 0, 0);
    hgemm_nt<128,128,2,4,4,5><<<dim3(8, 64), 256, SMEMB(128,128,4)>>>(
        p_kvln, p_Wvt, bv, nullptr, p_Vt, DMODEL, DMODEL, 0, 0);

    // 6. scores -> fp32 attn region (*0.125)
    hgemm_nt<128,128,2,4,4,6><<<dim3(8, 2, BBATCH*NHEADS), 256, SMEMB(128,128,4)>>>(
        p_Qh, p_Kh, nullptr, nullptr, attn, SKVLEN, DHEAD,
        (long)SQLEN*DHEAD, (long)SKVLEN*DHEAD);

    // 7. softmax in place + fp16 copy
    softmax_kernel<<<BBATCH*NHEADS*SQLEN, 256>>>(attn, p_attn_h);

    // 8. ctx = attn_h @ Vt^T -> fp16 row-major ctx
    hgemm_nt<128,64,4,2,4,7><<<dim3(1, 2, BBATCH*NHEADS), 256, SMEMB(128,64,4)>>>(
        p_attn_h, p_Vt, nullptr, nullptr, p_ctx, DHEAD, SKVLEN,
        (long)SQLEN*SKVLEN, (long)DHEAD*SKVLEN);

    // 9. x = ctx @ Wo + bo (fp32)
    hgemm_nt<64,128,2,4,4,0><<<dim3(8, 32), 256, SMEMB(64,128,4)>>>(
        p_ctx, p_Wot, bo, nullptr, p_x, DMODEL, DMODEL, 0, 0);

    // 10. y = LN_ff(x) -> fp16
    ln_h_kernel<<<QROWS, 256>>>(p_x, g_ff, b_ff, p_y);

    // 11. h = gelu(y @ W1 + b1) -> fp16
    hgemm_nt<128,128,2,4,4,1><<<dim3(32, 16), 256, SMEMB(128,128,4)>>>(
        p_y, p_W1t, b1, nullptr, p_h, DFFN, DMODEL, 0, 0);

    // 12. out = h @ W2 + b2 + x (fp32)
    hgemm_nt<64,128,2,4,4,2><<<dim3(8, 32), 256, SMEMB(64,128,4)>>>(
        p_h, p_W2t, b2, p_x, out, DMODEL, DFFN, 0, 0);
}

// round 7
// speedup vs baseline: 1.7657x; 1.0969x over previous
#include <cuda_runtime.h>
#include <cuda_fp16.h>
#include <math.h>
#include <stdint.h>

#define BBATCH 8
#define SQLEN  256
#define SKVLEN 1024
#define DMODEL 1024
#define NHEADS 16
#define DHEAD  64
#define DFFN   4096
#define QROWS  (BBATCH*SQLEN)
#define KVROWS (BBATCH*SKVLEN)
#define OUT_ELEMS  ((size_t)QROWS*DMODEL)
#define ATTN_ELEMS ((size_t)BBATCH*NHEADS*SQLEN*SKVLEN)

// ----------------------------- scratch -----------------------------------
__device__ __half g_qln_h [QROWS*DMODEL];
__device__ __half g_kvln_h[KVROWS*DMODEL];
__device__ __half g_Qh [QROWS*DMODEL];
__device__ __half g_Kh [KVROWS*DMODEL];
__device__ __half g_Vt [KVROWS*DMODEL];
__device__ __half g_attn_h[BBATCH*NHEADS*SQLEN*SKVLEN];
__device__ __half g_ctx_h[QROWS*DMODEL];
__device__ __half g_y_h [QROWS*DMODEL];
__device__ __half g_hh  [QROWS*DFFN];
__device__ __half g_Wqt[DMODEL*DMODEL];
__device__ __half g_Wkt[DMODEL*DMODEL];
__device__ __half g_Wvt[DMODEL*DMODEL];
__device__ __half g_Wot[DMODEL*DMODEL];
__device__ __half g_W1t[DFFN*DMODEL];
__device__ __half g_W2t[DMODEL*DFFN];
__device__ float  g_x [QROWS*DMODEL];
__device__ float  g_attn_fb[BBATCH*NHEADS*SQLEN*SKVLEN];

// ------------------ fused transposes ------------------------------------
__global__ void __launch_bounds__(256) transpose_all_kernel(
    const float* __restrict__ Wq, const float* __restrict__ Wk,
    const float* __restrict__ Wv, const float* __restrict__ Wo,
    const float* __restrict__ W1, const float* __restrict__ W2,
    __half* __restrict__ Wqt, __half* __restrict__ Wkt,
    __half* __restrict__ Wvt, __half* __restrict__ Wot,
    __half* __restrict__ W1t, __half* __restrict__ W2t)
{
    __shared__ float t[32][33];
    const int id = blockIdx.x;
    const float* W; __half* Wt; int K, N, local, tilesX;
    if (id < 4096) {
        K = DMODEL; N = DMODEL; tilesX = 32; local = id & 1023;
        const int w = id >> 10;
        W  = (w == 0) ? Wq  : (w == 1) ? Wk  : (w == 2) ? Wv  : Wo;
        Wt = (w == 0) ? Wqt : (w == 1) ? Wkt : (w == 2) ? Wvt : Wot;
    } else if (id < 8192) {
        K = DMODEL; N = DFFN; tilesX = 128; local = id - 4096; W = W1; Wt = W1t;
    } else {
        K = DFFN; N = DMODEL; tilesX = 32; local = id - 8192; W = W2; Wt = W2t;
    }
    const int n0 = (local % tilesX) * 32, k0 = (local / tilesX) * 32;
    const int x = threadIdx.x & 31, y = threadIdx.x >> 5;
    #pragma unroll
    for (int i = 0; i < 32; i += 8)
        t[y + i][x] = W[(size_t)(k0 + y + i) * N + n0 + x];
    __syncthreads();
    #pragma unroll
    for (int i = 0; i < 32; i += 8)
        Wt[(size_t)(n0 + y + i) * K + k0 + x] = __float2half_rn(t[x][y + i]);
}

// ----------------------------- LayerNorm -> fp16 -------------------------
__global__ void __launch_bounds__(256) ln_h_kernel(const float* __restrict__ x,
                                                   const float* __restrict__ g,
                                                   const float* __restrict__ b,
                                                   __half* __restrict__ y) {
    __shared__ float ssum[256], ssq[256];
    const int row = blockIdx.x, tid = threadIdx.x;
    const float4 xv = ((const float4*)(x + (size_t)row*DMODEL))[tid];
    ssum[tid] = xv.x + xv.y + xv.z + xv.w;
    ssq [tid] = xv.x*xv.x + xv.y*xv.y + xv.z*xv.z + xv.w*xv.w;
    __syncthreads();
    for (int st = 128; st > 0; st >>= 1) {
        if (tid < st) { ssum[tid] += ssum[tid+st]; ssq[tid] += ssq[tid+st]; }
        __syncthreads();
    }
    const float mu  = ssum[0] * (1.0f/DMODEL);
    const float inv = rsqrtf(ssq[0]*(1.0f/DMODEL) - mu*mu + 1e-5f);
    const float4 gv = ((const float4*)g)[tid];
    const float4 bv = ((const float4*)b)[tid];
    __half2* o = (__half2*)(y + (size_t)row*DMODEL) + tid*2;
    o[0] = __floats2half2_rn((xv.x - mu)*inv*gv.x + bv.x, (xv.y - mu)*inv*gv.y + bv.y);
    o[1] = __floats2half2_rn((xv.z - mu)*inv*gv.z + bv.z, (xv.w - mu)*inv*gv.w + bv.w);
}

// ---------------- softmax: fp32 in place + fp16 copy ---------------------
__global__ void __launch_bounds__(256) softmax_kernel(float* __restrict__ attn,
                                                      __half* __restrict__ attn_h) {
    __shared__ float red[256];
    const size_t row = blockIdx.x;
    float4* p = (float4*)(attn + row*(size_t)SKVLEN);
    const int tid = threadIdx.x;
    float4 v = p[tid];
    float m = fmaxf(fmaxf(v.x, v.y), fmaxf(v.z, v.w));
    red[tid] = m; __syncthreads();
    for (int st = 128; st > 0; st >>= 1) { if (tid < st) red[tid] = fmaxf(red[tid], red[tid+st]); __syncthreads(); }
    m = red[0]; __syncthreads();
    v.x = __expf(v.x - m); v.y = __expf(v.y - m); v.z = __expf(v.z - m); v.w = __expf(v.w - m);
    red[tid] = v.x + v.y + v.z + v.w; __syncthreads();
    for (int st = 128; st > 0; st >>= 1) { if (tid < st) red[tid] += red[tid+st]; __syncthreads(); }
    const float inv = 1.0f / red[0];
    v.x *= inv; v.y *= inv; v.z *= inv; v.w *= inv;
    p[tid] = v;
    __half2* ph = (__half2*)(attn_h + row*(size_t)SKVLEN) + tid*2;
    ph[0] = __floats2half2_rn(v.x, v.y);
    ph[1] = __floats2half2_rn(v.z, v.w);
}

// ----------------------------- fp16 MMA helpers --------------------------
__device__ __forceinline__ void ldsm4(uint32_t (&d)[4], uint32_t addr) {
    asm volatile("ldmatrix.sync.aligned.m8n8.x4.shared.b16 {%0,%1,%2,%3}, [%4];"
        : "=r"(d[0]), "=r"(d[1]), "=r"(d[2]), "=r"(d[3]) : "r"(addr));
}
__device__ __forceinline__ void mma_f16(float (&c)[4], const uint32_t (&a)[4],
                                        const uint32_t (&b)[2]) {
    asm volatile("mma.sync.aligned.m16n8k16.row.col.f32.f16.f16.f32 "
        "{%0,%1,%2,%3},{%4,%5,%6,%7},{%8,%9},{%0,%1,%2,%3};"
        : "+f"(c[0]), "+f"(c[1]), "+f"(c[2]), "+f"(c[3])
        : "r"(a[0]), "r"(a[1]), "r"(a[2]), "r"(a[3]), "r"(b[0]), "r"(b[1]));
}

// Epilogue modes (unchanged semantics)
template<int MODE>
__device__ __forceinline__ void store_elem(void* __restrict__ Cv,
                                           const float* __restrict__ bias,
                                           const float* __restrict__ res,
                                           int N, int bz, int row, int col, float v) {
    if (MODE == 0) {
        ((float*)Cv)[(size_t)row*N + col] = v + bias[col];
    } else if (MODE == 1) {
        float x = v + bias[col];
        ((__half*)Cv)[(size_t)row*N + col] =
            __float2half_rn(0.5f*x*(1.0f + erff(x*0.70710678118654752f)));
    } else if (MODE == 2) {
        ((float*)Cv)[(size_t)row*N + col] = v + bias[col] + res[(size_t)row*N + col];
    } else if (MODE == 3) {
        ((__half*)Cv)[(size_t)(row>>8)*(NHEADS*SQLEN*DHEAD) + (size_t)(col>>6)*(SQLEN*DHEAD)
          + (size_t)(row&255)*DHEAD + (col&63)] = __float2half_rn(v + bias[col]);
    } else if (MODE == 4) {
        ((__half*)Cv)[(size_t)(row>>10)*(NHEADS*SKVLEN*DHEAD) + (size_t)(col>>6)*(SKVLEN*DHEAD)
          + (size_t)(row&1023)*DHEAD + (col&63)] = __float2half_rn(v + bias[col]);
    } else if (MODE == 5) {
        ((__half*)Cv)[(size_t)(row>>10)*(NHEADS*DHEAD*SKVLEN) + (size_t)(col>>6)*(DHEAD*SKVLEN)
          + (size_t)(col&63)*SKVLEN + (row&1023)] = __float2half_rn(v + bias[col]);
    } else if (MODE == 6) {
        ((float*)Cv)[(size_t)bz*(SQLEN*SKVLEN) + (size_t)row*SKVLEN + col] = v * 0.125f;
    } else if (MODE == 7) {
        ((__half*)Cv)[((size_t)(bz>>4)*SQLEN + row)*DMODEL + (size_t)(bz&15)*DHEAD + col] =
            __float2half_rn(v);
    }
}

// ---- fp16 NT GEMM with register-level fragment double-buffering ---------
// CTA tile BM x BN, warp tile (BM/WM) x (BN/WN), BK=32, STAGES-deep cp.async.
template<int BM, int BN, int WM, int WN, int STAGES, int MODE>
__global__ void __launch_bounds__(WM*WN*32, 3) hgemm_nt(
    const __half* __restrict__ Ag, const __half* __restrict__ Bg,
    const float* __restrict__ bias, const float* __restrict__ res,
    void* __restrict__ Cg, int N, int K, long sA, long sB)
{
    constexpr int NTH  = WM*WN*32;
    constexpr int ROWB = 80;                       // 32 halves + 8 pad
    constexpr int STGB = (BM + BN) * ROWB;
    constexpr int MT = BM / (WM * 16);
    constexpr int NT = BN / (WN * 8);
    extern __shared__ __align__(16) __half dynsm[];
    const uint32_t sm0 = (uint32_t)__cvta_generic_to_shared(dynsm);

    const int tid  = threadIdx.x;
    const int warp = tid >> 5, lane = tid & 31;
    const int wm0 = (warp % WM) * (BM / WM);
    const int wn0 = (warp / WM) * (BN / WN);
    const int bm0 = blockIdx.y * BM;
    const int bn0 = blockIdx.x * BN;
    const int bz  = blockIdx.z;
    const __half* A = Ag + (size_t)bz * sA + (size_t)bm0 * K;
    const __half* B = Bg + (size_t)bz * sB + (size_t)bn0 * K;

    float acc[MT][NT][4];
    #pragma unroll
    for (int i = 0; i < MT; ++i)
        #pragma unroll
        for (int j = 0; j < NT; ++j)
            { acc[i][j][0]=0.f; acc[i][j][1]=0.f; acc[i][j][2]=0.f; acc[i][j][3]=0.f; }

    const int KT = K >> 5;

    auto prefetch = [&](int it) {
        if (it < KT) {
            const uint32_t sb = sm0 + (uint32_t)(it % STAGES) * STGB;
            const __half* Ak = A + it * 32;
            const __half* Bk = B + it * 32;
            #pragma unroll
            for (int i = tid; i < (BM + BN) * 4; i += NTH) {
                const int r = i >> 2, c = i & 3;
                uint32_t dst; const __half* src;
                if (r < BM) { dst = sb + (uint32_t)(r*ROWB + c*16); src = Ak + (size_t)r*K + c*8; }
                else { dst = sb + (uint32_t)(BM*ROWB + (r-BM)*ROWB + c*16);
                       src = Bk + (size_t)(r-BM)*K + c*8; }
                asm volatile("cp.async.cg.shared.global [%0], [%1], 16;" :: "r"(dst), "l"(src));
            }
        }
        asm volatile("cp.async.commit_group;" ::: "memory");
    };

    uint32_t afA[MT][4], bfA[NT][2], afB[MT][4], bfB[NT][2];
    const int lr = lane & 15;

    auto ldfrag = [&](uint32_t sbA, uint32_t sbB, int ks,
                      uint32_t (&af)[MT][4], uint32_t (&bf)[NT][2]) {
        const int lcb = ((lane >> 4) * 8 + ks * 16) * 2;
        #pragma unroll
        for (int mt = 0; mt < MT; ++mt)
            ldsm4(af[mt], sbA + (uint32_t)((wm0 + mt*16 + lr)*ROWB + lcb));
        #pragma unroll
        for (int nt2 = 0; nt2 < NT/2; ++nt2) {
            uint32_t d[4];
            ldsm4(d, sbB + (uint32_t)((wn0 + nt2*16 + lr)*ROWB + lcb));
            bf[nt2*2  ][0] = d[0]; bf[nt2*2  ][1] = d[2];
            bf[nt2*2+1][0] = d[1]; bf[nt2*2+1][1] = d[3];
        }
    };
    auto mma_all = [&](const uint32_t (&af)[MT][4], const uint32_t (&bf)[NT][2]) {
        #pragma unroll
        for (int mt = 0; mt < MT; ++mt)
            #pragma unroll
            for (int nt = 0; nt < NT; ++nt)
                mma_f16(acc[mt][nt], af[mt], bf[nt]);
    };

    #pragma unroll
    for (int p = 0; p < STAGES - 1; ++p) prefetch(p);
    asm volatile("cp.async.wait_group %0;" :: "n"(STAGES - 2) : "memory");
    __syncthreads();
    ldfrag(sm0, sm0 + BM*ROWB, 0, afA, bfA);

    for (int kt = 0; kt < KT; ++kt) {
        const uint32_t sbA = sm0 + (uint32_t)(kt % STAGES) * STGB;
        ldfrag(sbA, sbA + BM*ROWB, 1, afB, bfB);    // ks=1 frags (overlaps mma below)
        mma_all(afA, bfA);                           // ks=0 MMAs
        prefetch(kt + STAGES - 1);
        if (kt + 1 < KT) {
            asm volatile("cp.async.wait_group %0;" :: "n"(STAGES - 2) : "memory");
            __syncthreads();
            const uint32_t nA = sm0 + (uint32_t)((kt + 1) % STAGES) * STGB;
            ldfrag(nA, nA + BM*ROWB, 0, afA, bfA);  // next tile ks=0 frags
        }
        mma_all(afB, bfB);                           // ks=1 MMAs
    }

    const int g = lane >> 2, t = lane & 3;
    #pragma unroll
    for (int mt = 0; mt < MT; ++mt) {
        #pragma unroll
        for (int nt = 0; nt < NT; ++nt) {
            const int r0 = bm0 + wm0 + mt*16 + g;
            const int c0 = bn0 + wn0 + nt*8 + t*2;
            store_elem<MODE>(Cg, bias, res, N, bz, r0,     c0,     acc[mt][nt][0]);
            store_elem<MODE>(Cg, bias, res, N, bz, r0,     c0 + 1, acc[mt][nt][1]);
            store_elem<MODE>(Cg, bias, res, N, bz, r0 + 8, c0,     acc[mt][nt][2]);
            store_elem<MODE>(Cg, bias, res, N, bz, r0 + 8, c0 + 1, acc[mt][nt][3]);
        }
    }
}

// ----------------------------- launch ------------------------------------
#define SMEMB(BM, BN, S) ((S) * ((BM) + (BN)) * 80)

extern "C" void kernel_launch(void* const* d_in, const int* in_sizes, int n_in,
                              void* d_out, int out_size) {
    const float* memory = (const float*)d_in[0];
    const float* q      = (const float*)d_in[1];
    const float* Wq = (const float*)d_in[2];  const float* bq = (const float*)d_in[3];
    const float* Wk = (const float*)d_in[4];  const float* bk = (const float*)d_in[5];
    const float* Wv = (const float*)d_in[6];  const float* bv = (const float*)d_in[7];
    const float* Wo = (const float*)d_in[8];  const float* bo = (const float*)d_in[9];
    const float* g_kv = (const float*)d_in[10]; const float* b_kv = (const float*)d_in[11];
    const float* g_q  = (const float*)d_in[12]; const float* b_q  = (const float*)d_in[13];
    const float* g_ff = (const float*)d_in[14]; const float* b_ff = (const float*)d_in[15];
    const float* W1 = (const float*)d_in[16]; const float* b1 = (const float*)d_in[17];
    const float* W2 = (const float*)d_in[18]; const float* b2 = (const float*)d_in[19];

    __half *p_qln, *p_kvln, *p_Qh, *p_Kh, *p_Vt, *p_attn_h, *p_ctx, *p_y, *p_h;
    __half *p_Wqt, *p_Wkt, *p_Wvt, *p_Wot, *p_W1t, *p_W2t;
    float *p_x, *p_fb;
    cudaGetSymbolAddress((void**)&p_qln,  g_qln_h);
    cudaGetSymbolAddress((void**)&p_kvln, g_kvln_h);
    cudaGetSymbolAddress((void**)&p_Qh,   g_Qh);
    cudaGetSymbolAddress((void**)&p_Kh,   g_Kh);
    cudaGetSymbolAddress((void**)&p_Vt,   g_Vt);
    cudaGetSymbolAddress((void**)&p_attn_h, g_attn_h);
    cudaGetSymbolAddress((void**)&p_ctx,  g_ctx_h);
    cudaGetSymbolAddress((void**)&p_y,    g_y_h);
    cudaGetSymbolAddress((void**)&p_h,    g_hh);
    cudaGetSymbolAddress((void**)&p_Wqt,  g_Wqt);
    cudaGetSymbolAddress((void**)&p_Wkt,  g_Wkt);
    cudaGetSymbolAddress((void**)&p_Wvt,  g_Wvt);
    cudaGetSymbolAddress((void**)&p_Wot,  g_Wot);
    cudaGetSymbolAddress((void**)&p_W1t,  g_W1t);
    cudaGetSymbolAddress((void**)&p_W2t,  g_W2t);
    cudaGetSymbolAddress((void**)&p_x,    g_x);
    cudaGetSymbolAddress((void**)&p_fb,   g_attn_fb);

    float* out = (float*)d_out;
    float* attn = ((size_t)out_size >= OUT_ELEMS + ATTN_ELEMS) ? (out + OUT_ELEMS) : p_fb;

    // 0. all weight transposes in one launch
    transpose_all_kernel<<<12288, 256>>>(Wq, Wk, Wv, Wo, W1, W2,
                                         p_Wqt, p_Wkt, p_Wvt, p_Wot, p_W1t, p_W2t);

    // 1-2. pre-norms -> fp16
    ln_h_kernel<<<KVROWS, 256>>>(memory, g_kv, b_kv, p_kvln);
    ln_h_kernel<<<QROWS,  256>>>(q,      g_q,  b_q,  p_qln);

    // 3-5. QKV projections (64x128 tiles, 128 threads)
    hgemm_nt<64,128,2,2,3,3><<<dim3(8, 32), 128, SMEMB(64,128,3)>>>(
        p_qln,  p_Wqt, bq, nullptr, p_Qh, DMODEL, DMODEL, 0, 0);
    hgemm_nt<64,128,2,2,3,4><<<dim3(8, 128), 128, SMEMB(64,128,3)>>>(
        p_kvln, p_Wkt, bk, nullptr, p_Kh, DMODEL, DMODEL, 0, 0);
    hgemm_nt<64,128,2,2,3,5><<<dim3(8, 128), 128, SMEMB(64,128,3)>>>(
        p_kvln, p_Wvt, bv, nullptr, p_Vt, DMODEL, DMODEL, 0, 0);

    // 6. scores -> fp32 attn region (*0.125), K=64
    hgemm_nt<64,128,2,2,3,6><<<dim3(8, 4, BBATCH*NHEADS), 128, SMEMB(64,128,3)>>>(
        p_Qh, p_Kh, nullptr, nullptr, attn, SKVLEN, DHEAD,
        (long)SQLEN*DHEAD, (long)SKVLEN*DHEAD);

    // 7. softmax in place + fp16 copy
    softmax_kernel<<<BBATCH*NHEADS*SQLEN, 256>>>(attn, p_attn_h);

    // 8. ctx = attn_h @ Vt^T (N=64 -> 64x64 tiles)
    hgemm_nt<64,64,2,2,3,7><<<dim3(1, 4, BBATCH*NHEADS), 128, SMEMB(64,64,3)>>>(
        p_attn_h, p_Vt, nullptr, nullptr, p_ctx, DHEAD, SKVLEN,
        (long)SQLEN*SKVLEN, (long)DHEAD*SKVLEN);

    // 9. x = ctx @ Wo + bo (fp32)
    hgemm_nt<64,128,2,2,3,0><<<dim3(8, 32), 128, SMEMB(64,128,3)>>>(
        p_ctx, p_Wot, bo, nullptr, p_x, DMODEL, DMODEL, 0, 0);

    // 10. y = LN_ff(x) -> fp16
    ln_h_kernel<<<QROWS, 256>>>(p_x, g_ff, b_ff, p_y);

    // 11. h = gelu(y @ W1 + b1) -> fp16
    hgemm_nt<64,128,2,2,3,1><<<dim3(32, 32), 128, SMEMB(64,128,3)>>>(
        p_y, p_W1t, b1, nullptr, p_h, DFFN, DMODEL, 0, 0);

    // 12. out = h @ W2 + b2 + x (fp32)
    hgemm_nt<64,128,2,2,3,2><<<dim3(8, 32), 128, SMEMB(64,128,3)>>>(
        p_h, p_W2t, b2, p_x, out, DMODEL, DFFN, 0, 0);
}